// round 1
// baseline (speedup 1.0000x reference)
#include <cuda_runtime.h>
#include <cstddef>

// ---------------------------------------------------------------------------
// Scratch (device globals — no allocation allowed)
// ---------------------------------------------------------------------------
__device__ __align__(16) float g_Fpart[128 * 128]; // per-block partial f
__device__ __align__(16) float g_feat[452];        // feat  (450)
__device__ __align__(16) float g_h[452];           // relu(ext_W1@feat+b1)
__device__ __align__(16) float g_feat2[452];       // ext_W2@h+b2
__device__ __align__(16) float g_h2[452];          // relu(dec_W1@feat2+db1)

// ---------------------------------------------------------------------------
// Stage 1: f[i] = sum_{t,p,c} xw[t,p,c] * TwE[t,i] * PE[p,i] * CE[c,i]
// 128 blocks x 128 threads. Block b handles rows tp in [b*8, b*8+8).
// Thread layout: iq = tid&31 -> i = 4*iq..4*iq+3 ; rq = tid>>5 -> rows rq*2, rq*2+1.
// Writes g_Fpart[b*128 + i] (deterministic smem reduction, no atomics).
// ---------------------------------------------------------------------------
__global__ void k_stage1(const float* __restrict__ x, const float* __restrict__ TwE,
                         const float* __restrict__ PE, const float* __restrict__ CE,
                         int xoff)
{
    const int tid = threadIdx.x;
    const int iq  = tid & 31;
    const int rq  = tid >> 5;          // warp id 0..3
    const int i0  = iq * 4;
    const int row0 = blockIdx.x * 8 + rq * 2;   // tp index, [0,1024)

    const float* xb  = x + xoff;
    const float* xr0 = xb + row0 * 128;
    const float* xr1 = xr0 + 128;

    float a00 = 0.f, a01 = 0.f, a02 = 0.f, a03 = 0.f;
    float a10 = 0.f, a11 = 0.f, a12 = 0.f, a13 = 0.f;

    #pragma unroll 4
    for (int c = 0; c < 128; ++c) {
        const float4 ce = *reinterpret_cast<const float4*>(CE + c * 128 + i0);
        const float x0 = __ldg(xr0 + c);
        const float x1 = __ldg(xr1 + c);
        a00 += x0 * ce.x; a01 += x0 * ce.y; a02 += x0 * ce.z; a03 += x0 * ce.w;
        a10 += x1 * ce.x; a11 += x1 * ce.y; a12 += x1 * ce.z; a13 += x1 * ce.w;
    }

    const int t  = row0 >> 8;          // same t for both rows (8 | 256)
    const int p0 = row0 & 255;
    const int p1 = (row0 + 1) & 255;

    const float4 tw  = *reinterpret_cast<const float4*>(TwE + t  * 128 + i0);
    const float4 pe0 = *reinterpret_cast<const float4*>(PE  + p0 * 128 + i0);
    const float4 pe1 = *reinterpret_cast<const float4*>(PE  + p1 * 128 + i0);

    float v0 = (a00 * pe0.x + a10 * pe1.x) * tw.x;
    float v1 = (a01 * pe0.y + a11 * pe1.y) * tw.y;
    float v2 = (a02 * pe0.z + a12 * pe1.z) * tw.z;
    float v3 = (a03 * pe0.w + a13 * pe1.w) * tw.w;

    __shared__ float sbuf[4][128];
    sbuf[rq][i0 + 0] = v0;
    sbuf[rq][i0 + 1] = v1;
    sbuf[rq][i0 + 2] = v2;
    sbuf[rq][i0 + 3] = v3;
    __syncthreads();

    if (rq == 0) {
        float4 s;
        s.x = sbuf[0][i0+0] + sbuf[1][i0+0] + sbuf[2][i0+0] + sbuf[3][i0+0];
        s.y = sbuf[0][i0+1] + sbuf[1][i0+1] + sbuf[2][i0+1] + sbuf[3][i0+1];
        s.z = sbuf[0][i0+2] + sbuf[1][i0+2] + sbuf[2][i0+2] + sbuf[3][i0+2];
        s.w = sbuf[0][i0+3] + sbuf[1][i0+3] + sbuf[2][i0+3] + sbuf[3][i0+3];
        *reinterpret_cast<float4*>(g_Fpart + blockIdx.x * 128 + i0) = s;
    }
}

// ---------------------------------------------------------------------------
// feat = mE @ f, where f = reduce(g_Fpart). Each block does its own (cheap,
// deterministic) reduction of the 128 partials, then warp-per-row matvec.
// grid 57 x 256 (456 warps >= 450 rows).
// ---------------------------------------------------------------------------
__global__ void k_feat(const float* __restrict__ mE)
{
    __shared__ float sf[128];
    __shared__ float stmp[128];

    const int tid  = threadIdx.x;
    const int i    = tid & 127;
    const int half = tid >> 7;

    {
        float s0 = 0.f, s1 = 0.f, s2 = 0.f, s3 = 0.f;
        const int b0 = half * 64;
        #pragma unroll 4
        for (int b = b0; b < b0 + 64; b += 4) {
            s0 += g_Fpart[(b + 0) * 128 + i];
            s1 += g_Fpart[(b + 1) * 128 + i];
            s2 += g_Fpart[(b + 2) * 128 + i];
            s3 += g_Fpart[(b + 3) * 128 + i];
        }
        const float s = (s0 + s1) + (s2 + s3);
        if (half) stmp[i] = s;
        __syncthreads();
        if (!half) sf[i] = s + stmp[i];
        __syncthreads();
    }

    const int row  = blockIdx.x * 8 + (tid >> 5);
    const int lane = tid & 31;
    if (row < 450) {
        const float* r = mE + row * 128;
        float acc = r[lane]       * sf[lane]
                  + r[lane + 32]  * sf[lane + 32]
                  + r[lane + 64]  * sf[lane + 64]
                  + r[lane + 96]  * sf[lane + 96];
        #pragma unroll
        for (int o = 16; o; o >>= 1) acc += __shfl_xor_sync(0xFFFFFFFFu, acc, o);
        if (lane == 0) g_feat[row] = acc;
    }
}

// ---------------------------------------------------------------------------
// Generic 450x450 matvec: vout = [relu](W @ vin + b)
// src/dst select among the device scratch vectors. Warp-per-row, float2 loads.
// grid 57 x 256.
// ---------------------------------------------------------------------------
__global__ void k_mv450(const float* __restrict__ W, const float* __restrict__ b,
                        int src, int dst, int do_relu)
{
    const float* vin  = (src == 0) ? g_feat : (src == 1) ? g_h : g_feat2;
    float*       vout = (dst == 0) ? g_h    : (dst == 1) ? g_feat2 : g_h2;

    __shared__ float2 sv[226];
    const int tid = threadIdx.x;
    if (tid < 225) sv[tid] = reinterpret_cast<const float2*>(vin)[tid];
    __syncthreads();

    const int row  = blockIdx.x * 8 + (tid >> 5);
    const int lane = tid & 31;
    if (row >= 450) return;

    const float2* wr = reinterpret_cast<const float2*>(W + (size_t)row * 450);
    float acc = 0.f;
    #pragma unroll
    for (int j = 0; j < 7; ++j) {
        const float2 w = wr[lane + 32 * j];
        const float2 v = sv[lane + 32 * j];
        acc += w.x * v.x + w.y * v.y;
    }
    if (lane == 0) {                     // 225 = 7*32 + 1 tail element
        const float2 w = wr[224];
        const float2 v = sv[224];
        acc += w.x * v.x + w.y * v.y;
    }
    #pragma unroll
    for (int o = 16; o; o >>= 1) acc += __shfl_xor_sync(0xFFFFFFFFu, acc, o);
    if (lane == 0) {
        float r = acc + b[row];
        vout[row] = do_relu ? fmaxf(r, 0.f) : r;
    }
}

// ---------------------------------------------------------------------------
// out = dec_W2 @ h2 + dec_b2   (131072 x 450) — the HBM-bound kernel.
// Warp-per-row, 8 independent coalesced LDG.64 per lane. grid 16384 x 256.
// ---------------------------------------------------------------------------
__global__ void k_dec(const float* __restrict__ W, const float* __restrict__ b,
                      float* __restrict__ out)
{
    __shared__ float2 sv[226];
    const int tid = threadIdx.x;
    if (tid < 225) sv[tid] = reinterpret_cast<const float2*>(g_h2)[tid];
    __syncthreads();

    const int row  = blockIdx.x * 8 + (tid >> 5);
    const int lane = tid & 31;

    const float2* wr = reinterpret_cast<const float2*>(W + (size_t)row * 450);
    float acc = 0.f;
    #pragma unroll
    for (int j = 0; j < 7; ++j) {
        const float2 w = wr[lane + 32 * j];
        const float2 v = sv[lane + 32 * j];
        acc += w.x * v.x + w.y * v.y;
    }
    if (lane == 0) {
        const float2 w = wr[224];
        const float2 v = sv[224];
        acc += w.x * v.x + w.y * v.y;
    }
    #pragma unroll
    for (int o = 16; o; o >>= 1) acc += __shfl_xor_sync(0xFFFFFFFFu, acc, o);
    if (lane == 0) out[row] = acc + b[row];
}

// ---------------------------------------------------------------------------
// Launcher (graph-capturable: kernel launches on the default stream only)
// Input order per metadata: x, t, TwE, PE, CE, mE, ext_W1, ext_b1, ext_W2,
// ext_b2, dec_W1, dec_b1, dec_W2, dec_b2
// ---------------------------------------------------------------------------
extern "C" void kernel_launch(void* const* d_in, const int* in_sizes, int n_in,
                              void* d_out, int out_size)
{
    const float* x   = (const float*)d_in[0];
    const float* TwE = (const float*)d_in[2];
    const float* PE  = (const float*)d_in[3];
    const float* CE  = (const float*)d_in[4];
    const float* mE  = (const float*)d_in[5];
    const float* eW1 = (const float*)d_in[6];
    const float* eb1 = (const float*)d_in[7];
    const float* eW2 = (const float*)d_in[8];
    const float* eb2 = (const float*)d_in[9];
    const float* dW1 = (const float*)d_in[10];
    const float* db1 = (const float*)d_in[11];
    const float* dW2 = (const float*)d_in[12];
    const float* db2 = (const float*)d_in[13];
    float* out = (float*)d_out;

    const int xoff = in_sizes[0] - 4 * 256 * 128;   // last SLIDING_WINDOW=4 steps

    k_stage1<<<128, 128>>>(x, TwE, PE, CE, xoff);
    k_feat  <<<57, 256>>>(mE);
    k_mv450 <<<57, 256>>>(eW1, eb1, /*src=*/0, /*dst=*/0, /*relu=*/1); // g_feat -> g_h
    k_mv450 <<<57, 256>>>(eW2, eb2, /*src=*/1, /*dst=*/1, /*relu=*/0); // g_h    -> g_feat2
    k_mv450 <<<57, 256>>>(dW1, db1, /*src=*/2, /*dst=*/2, /*relu=*/1); // g_feat2-> g_h2
    k_dec   <<<16384, 256>>>(dW2, db2, out);
    (void)n_in; (void)out_size;
}

// round 2
// speedup vs baseline: 1.3852x; 1.3852x over previous
#include <cuda_runtime.h>
#include <cstddef>

// ---------------------------------------------------------------------------
// Persistent fused kernel: 148 blocks x 1024 threads (all co-resident),
// stages separated by a global sense-reversal barrier.
// ---------------------------------------------------------------------------
#define NBLK   148
#define NTHR   1024
#define NWARPS (NBLK * 32)          // 4736 warps chip-wide
#define NROWS_DEC 131072            // 4*P*C
#define MDIM   450

// Scratch (device globals; zero device allocation)
__device__ __align__(16) float g_Fpart[32 * 128]; // stage-1 partials (blocks 0..31)
__device__ __align__(16) float g_feat[452];
__device__ __align__(16) float g_h[452];
__device__ __align__(16) float g_feat2[452];
__device__ __align__(16) float g_h2[452];

// Grid barrier state (monotonic generation => safe across graph replays)
__device__ unsigned g_count = 0;
__device__ volatile unsigned g_gen = 0;

__device__ __forceinline__ void grid_bar()
{
    __syncthreads();
    if (threadIdx.x == 0) {
        const unsigned gen = g_gen;        // stable: only bumped at this barrier's release
        __threadfence();                   // publish this block's prior stores
        if (atomicAdd(&g_count, 1u) == (unsigned)gridDim.x - 1u) {
            atomicExch(&g_count, 0u);
            __threadfence();
            g_gen = gen + 1u;              // release
        } else {
            while (g_gen == gen) { }       // volatile spin (L2)
            __threadfence();               // acquire
        }
    }
    __syncthreads();
}

// Warp-per-row 450x450 matvec stage: vout = [relu](W @ vin + b).
// Active on blocks 0..14 (32 warps each -> 450 rows). sh must hold 452 floats.
__device__ __forceinline__ void mv450_stage(const float* __restrict__ W,
                                            const float* __restrict__ b,
                                            const float* __restrict__ vin_g,
                                            float* __restrict__ vout_g,
                                            bool do_relu, float* sh)
{
    const int tid = threadIdx.x;
    if (blockIdx.x < 15) {
        if (tid < MDIM) sh[tid] = __ldcg(vin_g + tid);
        __syncthreads();

        const int wid  = tid >> 5;
        const int lane = tid & 31;
        const int row  = blockIdx.x * 32 + wid;
        if (row < MDIM) {
            const float2* wr = reinterpret_cast<const float2*>(W + (size_t)row * MDIM);
            const float2* sv = reinterpret_cast<const float2*>(sh);
            float acc = 0.f;
            #pragma unroll
            for (int j = 0; j < 7; ++j) {
                const float2 w = __ldg(wr + lane + 32 * j);
                const float2 v = sv[lane + 32 * j];
                acc += w.x * v.x + w.y * v.y;
            }
            if (lane == 0) {               // 225 float2 = 7*32 + 1 tail
                const float2 w = __ldg(wr + 224);
                const float2 v = sv[224];
                acc += w.x * v.x + w.y * v.y;
            }
            #pragma unroll
            for (int o = 16; o; o >>= 1) acc += __shfl_xor_sync(0xFFFFFFFFu, acc, o);
            if (lane == 0) {
                float r = acc + __ldg(b + row);
                vout_g[row] = do_relu ? fmaxf(r, 0.f) : r;
            }
        }
    }
}

__global__ void __launch_bounds__(NTHR, 1)
fused_kernel(const float* __restrict__ x,   const float* __restrict__ TwE,
             const float* __restrict__ PE,  const float* __restrict__ CE,
             const float* __restrict__ mE,
             const float* __restrict__ eW1, const float* __restrict__ eb1,
             const float* __restrict__ eW2, const float* __restrict__ eb2,
             const float* __restrict__ dW1, const float* __restrict__ db1,
             const float* __restrict__ dW2, const float* __restrict__ db2,
             float* __restrict__ out, int xoff)
{
    __shared__ float sh[32 * 128];          // 16KB, reused per stage
    const int tid  = threadIdx.x;
    const int wid  = tid >> 5;
    const int lane = tid & 31;
    const int blk  = blockIdx.x;

    // ---- Stage 1: per-(t,p)-row contributions, warp-per-row on blocks 0..31 ----
    // f[i] = sum_{t,p} TwE[t,i]*PE[p,i] * ( sum_c xw[t,p,c]*CE[c,i] )
    if (blk < 32) {
        const int row = blk * 32 + wid;      // tp in [0,1024)
        const int t   = row >> 8;
        const int p   = row & 255;
        const float* xr = x + xoff + row * 128;
        const int i0 = lane * 4;

        float a0 = 0.f, a1 = 0.f, a2 = 0.f, a3 = 0.f;
        #pragma unroll 4
        for (int c = 0; c < 128; ++c) {
            const float4 ce = *reinterpret_cast<const float4*>(CE + c * 128 + i0);
            const float  xv = __ldg(xr + c);
            a0 += xv * ce.x; a1 += xv * ce.y; a2 += xv * ce.z; a3 += xv * ce.w;
        }
        const float4 tw = *reinterpret_cast<const float4*>(TwE + t * 128 + i0);
        const float4 pe = *reinterpret_cast<const float4*>(PE  + p * 128 + i0);
        sh[wid * 128 + i0 + 0] = a0 * pe.x * tw.x;
        sh[wid * 128 + i0 + 1] = a1 * pe.y * tw.y;
        sh[wid * 128 + i0 + 2] = a2 * pe.z * tw.z;
        sh[wid * 128 + i0 + 3] = a3 * pe.w * tw.w;
        __syncthreads();
        if (tid < 128) {                     // block-local reduce over 32 warps
            float s = 0.f;
            #pragma unroll
            for (int w = 0; w < 32; ++w) s += sh[w * 128 + tid];
            g_Fpart[blk * 128 + tid] = s;
        }
    }
    grid_bar();

    // ---- Stage 2: feat = mE @ f  (blocks 0..14, warp-per-row) ----
    if (blk < 15) {
        if (tid < 128) {                     // f = reduce 32 partials
            float s = 0.f;
            #pragma unroll
            for (int b = 0; b < 32; ++b) s += __ldcg(&g_Fpart[b * 128 + tid]);
            sh[tid] = s;
        }
        __syncthreads();
        const int row = blk * 32 + wid;
        if (row < MDIM) {
            const float* r = mE + row * 128;
            float acc = __ldg(r + lane)       * sh[lane]
                      + __ldg(r + lane + 32)  * sh[lane + 32]
                      + __ldg(r + lane + 64)  * sh[lane + 64]
                      + __ldg(r + lane + 96)  * sh[lane + 96];
            #pragma unroll
            for (int o = 16; o; o >>= 1) acc += __shfl_xor_sync(0xFFFFFFFFu, acc, o);
            if (lane == 0) g_feat[row] = acc;
        }
    }
    grid_bar();

    // ---- Stage 3..5: the 450x450 chain ----
    mv450_stage(eW1, eb1, g_feat,  g_h,     true,  sh);
    grid_bar();
    mv450_stage(eW2, eb2, g_h,     g_feat2, false, sh);
    grid_bar();
    mv450_stage(dW1, db1, g_feat2, g_h2,    true,  sh);
    grid_bar();

    // ---- Stage 6: out = dec_W2 @ h2 + db2  (131072 x 450, HBM-bound) ----
    {
        for (int i = tid; i < MDIM; i += NTHR) sh[i] = __ldcg(&g_h2[i]);
        __syncthreads();
        const float2* sv = reinterpret_cast<const float2*>(sh);
        const int gw = blk * 32 + wid;       // global warp id, 0..4735
        const float2 vt = sv[224];

        for (int row = gw; row < NROWS_DEC; row += NWARPS) {
            const float2* wr = reinterpret_cast<const float2*>(dW2 + (size_t)row * MDIM);
            float acc = 0.f;
            #pragma unroll
            for (int j = 0; j < 7; ++j) {
                const float2 w = __ldcs(wr + lane + 32 * j);   // streaming: evict-first
                const float2 v = sv[lane + 32 * j];
                acc += w.x * v.x + w.y * v.y;
            }
            if (lane == 0) {
                const float2 w = __ldcs(wr + 224);
                acc += w.x * vt.x + w.y * vt.y;
            }
            #pragma unroll
            for (int o = 16; o; o >>= 1) acc += __shfl_xor_sync(0xFFFFFFFFu, acc, o);
            if (lane == 0) out[row] = acc + __ldg(db2 + row);
        }
    }
}

// ---------------------------------------------------------------------------
// Launcher: single persistent kernel launch (graph-capturable).
// Inputs: x, t, TwE, PE, CE, mE, ext_W1, ext_b1, ext_W2, ext_b2,
//         dec_W1, dec_b1, dec_W2, dec_b2
// ---------------------------------------------------------------------------
extern "C" void kernel_launch(void* const* d_in, const int* in_sizes, int n_in,
                              void* d_out, int out_size)
{
    const float* x   = (const float*)d_in[0];
    const float* TwE = (const float*)d_in[2];
    const float* PE  = (const float*)d_in[3];
    const float* CE  = (const float*)d_in[4];
    const float* mE  = (const float*)d_in[5];
    const float* eW1 = (const float*)d_in[6];
    const float* eb1 = (const float*)d_in[7];
    const float* eW2 = (const float*)d_in[8];
    const float* eb2 = (const float*)d_in[9];
    const float* dW1 = (const float*)d_in[10];
    const float* db1 = (const float*)d_in[11];
    const float* dW2 = (const float*)d_in[12];
    const float* db2 = (const float*)d_in[13];
    float* out = (float*)d_out;

    const int xoff = in_sizes[0] - 4 * 256 * 128;   // last SLIDING_WINDOW rows of x

    fused_kernel<<<NBLK, NTHR>>>(x, TwE, PE, CE, mE,
                                 eW1, eb1, eW2, eb2,
                                 dW1, db1, dW2, db2,
                                 out, xoff);
    (void)n_in; (void)out_size;
}